// round 14
// baseline (speedup 1.0000x reference)
#include <cuda_runtime.h>
#include <cuda_bf16.h>
#include <math.h>

// Problem constants (fixed by the reference)
#define BB 4
#define TT 512
#define TP 1024
#define CC 32
#define KK 128
#define NW 16                 // 32-bit words per 512-event mask
#define GPROWS (TT + CC)      // 544 GP rows per batch
#define NTHREADS 1024
#define TP_PER_BLOCK 32       // 1 tp per warp, 32 warps
#define LOG2E 1.4426950408889634f
#define EPSF 2.220446049250313e-16f

struct Smem {
    float    gp[GPROWS * CC];        // 68 KB: pa[e][c]*prefix-sum exp(pd*pt)
    float    pd2[CC * CC];           // (softplus(delta)[e][c]+EPS) * log2(e)
    float    pa[CC * CC];            // softplus(alpha)[e][c]
    float    t[TT];                  // batch's sorted event times
    float    gtg[TT];                // times grouped by event type
    int      ev[TT];                 // event ids
    unsigned mask[(NW + 1) * CC];    // [w][e] bitmask (word 16 = 0 pad)
    int      wpref[(NW + 1) * CC];   // [w][e] count below word w (word 16 = n)
    int      obase[CC];              // group start in gtg
    int      gbase[CC];              // group start row in gp
    int      gn[CC];                 // group sizes
    float    ex[KK];                 // cf logits -> exp(cf - max)
    int      ftc_s[KK];
    float    part[4 * CC];           // den partials (quarters, fixed order)
    float    pf[KK];                 // fine probs
    float    spmu[CC];               // softplus(mu)
};

// bare MUFU exp2 (independent of fast-math flags)
__device__ __forceinline__ float ex2(float x) {
    float y;
    asm("ex2.approx.ftz.f32 %0, %1;" : "=f"(y) : "f"(x));
    return y;
}

// fast softplus: abs err ~1e-6; amplified by pt<=25.6 in exponent -> <=2.5e-5 rel (ok vs 1e-3)
__device__ __forceinline__ float softplusf(float x) {
    return __logf(1.0f + __expf(x));
}

extern __shared__ char smem_raw[];

// One fused kernel: block = (tp-chunk, batch), grid 128, 1024 threads (32 warps).
// Each block rebuilds its batch's setup in shared, then evaluates 32 tp's (1/warp).
__global__ __launch_bounds__(NTHREADS) void fused_kernel(
    const int*   __restrict__ past_event,   // [B,T]
    const float* __restrict__ past_time,    // [B,T]
    const float* __restrict__ time_tensor,  // [B,TP]
    const float* __restrict__ mu,           // [C]
    const float* __restrict__ alpha,        // [C,C]
    const float* __restrict__ delta,        // [C,C]
    const float* __restrict__ cf,           // [K]
    const int*   __restrict__ ftc,          // [K]
    float*       __restrict__ out)          // [B,TP,K]
{
    Smem* s = reinterpret_cast<Smem*>(smem_raw);
    const int b    = blockIdx.y;
    const int tid  = threadIdx.x;
    const int lane = tid & 31;
    const int wrp  = tid >> 5;               // 0..31

    // ---- phase 1: global loads + softplus tables ----
    if (tid < TT) {
        s->ev[tid] = past_event[b * TT + tid];
        s->t[tid]  = past_time [b * TT + tid];
    }
    {   // CC*CC = 1024 = exactly one per thread
        s->pa[tid]  = softplusf(alpha[tid]);
        s->pd2[tid] = (softplusf(delta[tid]) + EPSF) * LOG2E;
    }
    if (tid < CC) s->spmu[tid] = softplusf(mu[tid]);
    if (tid < KK) { s->ex[tid] = cf[tid]; s->ftc_s[tid] = ftc[tid]; }
    __syncthreads();

    // ---- phase 2: event bitmasks via ballot (16 windows, warps 0..15) ----
    if (wrp < NW) {
        int evv = s->ev[wrp * 32 + lane];
        unsigned mym = 0u;
#pragma unroll
        for (int e = 0; e < CC; e++) {
            unsigned m = __ballot_sync(0xffffffffu, evv == e);
            if (lane == e) mym = m;
        }
        s->mask[wrp * CC + lane] = mym;
    }
    __syncthreads();

    // ---- phase 3a: warp0 = word-prefix + group-base scans; warp1 = cf max+exp ----
    if (wrp == 0) {
        int c = 0;
#pragma unroll
        for (int w = 0; w < NW; w++) {
            s->wpref[w * CC + lane] = c;
            c += __popc(s->mask[w * CC + lane]);
        }
        s->wpref[NW * CC + lane] = c;      // total n
        s->mask [NW * CC + lane] = 0u;     // pad word for J=512
        s->gn[lane] = c;
        int on = c, og = c + 1;            // inclusive scans
#pragma unroll
        for (int d = 1; d < 32; d <<= 1) {
            int v1 = __shfl_up_sync(0xffffffffu, on, d);
            int v2 = __shfl_up_sync(0xffffffffu, og, d);
            if (lane >= d) { on += v1; og += v2; }
        }
        s->obase[lane] = on - c;           // exclusive
        s->gbase[lane] = og - (c + 1);
    } else if (wrp == 1) {
        float a0 = s->ex[lane],      a1 = s->ex[lane + 32];
        float a2 = s->ex[lane + 64], a3 = s->ex[lane + 96];
        float m = fmaxf(fmaxf(a0, a1), fmaxf(a2, a3));
#pragma unroll
        for (int d = 16; d >= 1; d >>= 1)
            m = fmaxf(m, __shfl_xor_sync(0xffffffffu, m, d));
        float v0 = __expf(a0 - m), v1 = __expf(a1 - m);
        float v2 = __expf(a2 - m), v3 = __expf(a3 - m);
        __syncwarp();
        s->ex[lane] = v0; s->ex[lane + 32] = v1;
        s->ex[lane + 64] = v2; s->ex[lane + 96] = v3;
    }
    __syncthreads();

    // ---- phase 3b: scatter times into grouped order; den partials (fixed order) ----
    if (tid < TT) {
        int t = tid;
        int e = s->ev[t];
        int w = t >> 5, rb = t & 31;
        int j = s->wpref[w * CC + e]
              + __popc(s->mask[w * CC + e] & ((1u << rb) - 1u));
        s->gtg[s->obase[e] + j] = s->t[t];
    }
    if (wrp < 4) {   // warp q sums quarter q of k-space per c-lane, ascending k
        float d = 0.f;
#pragma unroll
        for (int kk = 0; kk < 32; kk++) {
            int k = wrp * 32 + kk;
            if (s->ftc_s[k] == lane) d += s->ex[k];
        }
        s->part[wrp * CC + lane] = d;
    }
    __syncthreads();

    // ---- phase 4: fine probs; GP prefix build (one group per warp) ----
    if (tid < KK) {
        int c = s->ftc_s[tid];
        float den = ((s->part[c] + s->part[CC + c]) + s->part[2 * CC + c])
                  + s->part[3 * CC + c];
        s->pf[tid] = s->ex[tid] / den;
    }
    {
        const int e  = wrp;
        const float pdv = s->pd2[e * CC + lane];   // includes log2e
        const float pav = s->pa[e * CC + lane];
        const int n  = s->gn[e];
        const int ob = s->obase[e];
        float* g = &s->gp[s->gbase[e] * CC];
        g[lane] = 0.f;                       // j = 0 row
        float acc = 0.f;
        int j = 0;
        for (; j + 4 <= n; j += 4) {         // pipeline 4 exps ahead of FADD chain
            float x0 = ex2(pdv * s->gtg[ob + j]);
            float x1 = ex2(pdv * s->gtg[ob + j + 1]);
            float x2 = ex2(pdv * s->gtg[ob + j + 2]);
            float x3 = ex2(pdv * s->gtg[ob + j + 3]);
            acc += x0; g[(j + 1) * CC + lane] = acc * pav;
            acc += x1; g[(j + 2) * CC + lane] = acc * pav;
            acc += x2; g[(j + 3) * CC + lane] = acc * pav;
            acc += x3; g[(j + 4) * CC + lane] = acc * pav;
        }
        for (; j < n; j++) {
            acc += ex2(pdv * s->gtg[ob + j]);
            g[(j + 1) * CC + lane] = acc * pav;
        }
    }
    __syncthreads();

    // ---- phase 5: main evaluation. one tp per warp; lane = c ----
    const int tp = blockIdx.x * TP_PER_BLOCK + wrp;
    const float tt  = time_tensor[b * TP + tp];
    const float ntt = -tt;

    // warp-parallel 2-level search: J = #events with (tt - pt) > EPS (monotone)
    int J;
    {
        unsigned m1 = __ballot_sync(0xffffffffu, tt - s->t[lane * 16 + 15] > EPSF);
        int base = 16 * __popc(m1);          // chunks fully below tt
        if (base == TT) {
            J = TT;
        } else {
            float tv = s->t[base + (lane & 15)];
            unsigned m2 = __ballot_sync(0xffffffffu,
                                        (lane < 16) && (tt - tv > EPSF));
            J = base + __popc(m2);
        }
    }

    // lane l resolves GP row for event-type e = l via bitmask popcount
    int rowl;
    {
        int wd = J >> 5, rb = J & 31;
        int jl = s->wpref[wd * CC + lane]
               + __popc(s->mask[wd * CC + lane] & ((1u << rb) - 1u));
        rowl = s->gbase[lane] + jl;
    }

    float acc = 0.f;
#pragma unroll
    for (int e = 0; e < CC; e++) {
        int r = __shfl_sync(0xffffffffu, rowl, e);
        float gpv = s->gp[r * CC + lane];               // conflict-free LDS
        float pdv = s->pd2[e * CC + lane];
        acc = fmaf(ex2(pdv * ntt), gpv, acc);
    }

    // epilogue: out[k] = (acc[ftc[k]] + spmu[c]) * pfine[k]
    float* o = out + (b * TP + tp) * KK;
#pragma unroll
    for (int j = 0; j < 4; j++) {
        int k = lane + 32 * j;
        int c = s->ftc_s[k];
        float v = __shfl_sync(0xffffffffu, acc, c);
        o[k] = (v + s->spmu[c]) * s->pf[k];
    }
}

// ---------------- launch ----------------
extern "C" void kernel_launch(void* const* d_in, const int* in_sizes, int n_in,
                              void* d_out, int out_size)
{
    const int*   past_event  = (const int*)  d_in[0];
    const float* past_time   = (const float*)d_in[1];
    const float* time_tensor = (const float*)d_in[2];
    const float* mu          = (const float*)d_in[3];
    const float* alpha       = (const float*)d_in[4];
    const float* delta       = (const float*)d_in[5];
    const float* cf_logits   = (const float*)d_in[6];
    const int*   ftc         = (const int*)  d_in[7];
    float* out = (float*)d_out;

    static_assert(sizeof(Smem) < 200 * 1024, "smem too large");
    cudaFuncSetAttribute(fused_kernel,
                         cudaFuncAttributeMaxDynamicSharedMemorySize,
                         (int)sizeof(Smem));
    fused_kernel<<<dim3(TP / TP_PER_BLOCK, BB), NTHREADS, sizeof(Smem)>>>(
        past_event, past_time, time_tensor, mu, alpha, delta, cf_logits, ftc, out);
}